// round 4
// baseline (speedup 1.0000x reference)
#include <cuda_runtime.h>
#include <math.h>

#define AT 48
#define SP 4
#define RCRf 5.2f
#define RCAf 3.5f
#define NSHFR 16
#define NSHFA 4
#define NSHFZ 8
#define RADSUB (SP * NSHFR)                 // 64
#define ANGSUB (NSHFA * NSHFZ)              // 32
#define NPAIRS_SP (SP * (SP + 1) / 2)       // 10
#define OUTW (RADSUB + NPAIRS_SP * ANGSUB)  // 384
#define NPAIR_A (AT * (AT - 1) / 2)         // 1128
#define PI_F 3.14159265358979f

__global__ __launch_bounds__(128) void aev_kernel(
    const float* __restrict__ coords,   // (M, A, 3)
    const float* __restrict__ gEtaR,    // (1,)
    const float* __restrict__ gShfR,    // (16,)
    const float* __restrict__ gEtaA,    // (1,)
    const float* __restrict__ gZeta,    // (1,)
    const float* __restrict__ gShfA,    // (4,)
    const float* __restrict__ gShfZ,    // (8,)
    const int*   __restrict__ species,  // (M, A)
    float* __restrict__ out)            // (M, A, 384)
{
    const int i = blockIdx.x;   // atom within molecule
    const int m = blockIdx.y;   // molecule
    const int tid = threadIdx.x;

    __shared__ float scx[AT], scy[AT], scz[AT];
    __shared__ int   ssp[AT];
    __shared__ float dxs[AT], dys[AT], dzs[AT], dds[AT];
    __shared__ float acc[OUTW];
    __shared__ float shfR[NSHFR], shfA[NSHFA], czv[NSHFZ], szv[NSHFZ];
    __shared__ float sEtaR, sEtaA, sZeta;

    // ---- stage molecule data + parameters ----
    if (tid < AT) {
        const float* c = coords + (size_t)(m * AT + tid) * 3;
        scx[tid] = c[0];
        scy[tid] = c[1];
        scz[tid] = c[2];
        ssp[tid] = species[m * AT + tid];
    }
    if (tid < NSHFR) shfR[tid] = gShfR[tid];
    if (tid < NSHFA) shfA[tid] = gShfA[tid];
    if (tid < NSHFZ) {
        float v = gShfZ[tid];
        czv[tid] = cosf(v);
        szv[tid] = sinf(v);
    }
    if (tid == 0) { sEtaR = gEtaR[0]; sEtaA = gEtaA[0]; sZeta = gZeta[0]; }
    for (int t = tid; t < OUTW; t += blockDim.x) acc[t] = 0.0f;
    __syncthreads();

    // ---- displacements from center atom i ----
    if (tid < AT) {
        float dx = scx[tid] - scx[i];
        float dy = scy[tid] - scy[i];
        float dz = scz[tid] - scz[i];
        dxs[tid] = dx; dys[tid] = dy; dzs[tid] = dz;
        dds[tid] = sqrtf(dx * dx + dy * dy + dz * dz);
    }
    __syncthreads();

    const float etaR = sEtaR, etaA = sEtaA, zeta = sZeta;

    // ---- radial part: neighbors j of i ----
    if (tid < AT && tid != i) {
        const int j = tid;
        const float d = dds[j];
        if (d <= RCRf) {
            const float fc = 0.5f * __cosf(d * (PI_F / RCRf)) + 0.5f;
            float* dst = acc + ssp[j] * NSHFR;
            #pragma unroll
            for (int s = 0; s < NSHFR; s++) {
                float t = d - shfR[s];
                float v = 0.25f * __expf(-etaR * t * t) * fc;
                atomicAdd(&dst[s], v);
            }
        }
    }

    // ---- angular part: pairs (j,k), j<k, both != i ----
    for (int p = tid; p < NPAIR_A; p += blockDim.x) {
        // decode triangular pair index -> (j, k) for AT=48
        int j = (int)((95.0f - sqrtf(9025.0f - 8.0f * (float)p)) * 0.5f);
        // fixups for fp rounding
        while (j > 0 && j * 47 - (j * (j - 1)) / 2 > p) j--;
        while ((j + 1) * 47 - ((j + 1) * j) / 2 <= p) j++;
        int k = p - (j * 47 - (j * (j - 1)) / 2) + j + 1;
        if (j == i || k == i) continue;

        const float d1 = dds[j];
        const float d2 = dds[k];
        if (d1 > RCAf || d2 > RCAf) continue;  // masked -> exact zero

        const float dot = dxs[j] * dxs[k] + dys[j] * dys[k] + dzs[j] * dzs[k];
        const float cosv = 0.95f * dot / (fmaxf(d1, 1e-8f) * fmaxf(d2, 1e-8f));
        const float sinv = sqrtf(fmaxf(1.0f - cosv * cosv, 0.0f));
        const float fcj = (0.5f * __cosf(d1 * (PI_F / RCAf)) + 0.5f) *
                          (0.5f * __cosf(d2 * (PI_F / RCAf)) + 0.5f);
        const float dm = 0.5f * (d1 + d2);

        float pre[NSHFA];
        #pragma unroll
        for (int a = 0; a < NSHFA; a++) {
            float t = dm - shfA[a];
            pre[a] = 2.0f * fcj * __expf(-etaA * t * t);
        }

        const int sa = ssp[j], sb = ssp[k];
        const int lo = min(sa, sb), hi = max(sa, sb);
        const int pidx = lo * SP - (lo * (lo - 1)) / 2 + (hi - lo);
        float* dst = acc + RADSUB + pidx * ANGSUB;

        #pragma unroll
        for (int z = 0; z < NSHFZ; z++) {
            // cos(theta - ShfZ[z]) expanded; sin(theta) >= 0 since theta in [0,pi]
            float cd = cosv * czv[z] + sinv * szv[z];
            float base = fmaxf(0.5f * (1.0f + cd), 0.0f);
            float f1 = __powf(base, zeta);
            #pragma unroll
            for (int a = 0; a < NSHFA; a++) {
                atomicAdd(&dst[a * NSHFZ + z], f1 * pre[a]);
            }
        }
    }

    __syncthreads();

    // ---- write out ----
    float* o = out + ((size_t)m * AT + i) * OUTW;
    for (int t = tid; t < OUTW; t += blockDim.x) o[t] = acc[t];
}

extern "C" void kernel_launch(void* const* d_in, const int* in_sizes, int n_in,
                              void* d_out, int out_size) {
    const float* coords = (const float*)d_in[0];
    const float* EtaR   = (const float*)d_in[1];
    const float* ShfR   = (const float*)d_in[2];
    const float* EtaA   = (const float*)d_in[3];
    const float* Zeta   = (const float*)d_in[4];
    const float* ShfA   = (const float*)d_in[5];
    const float* ShfZ   = (const float*)d_in[6];
    const int*   sp     = (const int*)d_in[7];
    float* out = (float*)d_out;

    const int M = in_sizes[0] / (AT * 3);
    dim3 grid(AT, M);
    aev_kernel<<<grid, 128>>>(coords, EtaR, ShfR, EtaA, Zeta, ShfA, ShfZ, sp, out);
}

// round 6
// speedup vs baseline: 1.2291x; 1.2291x over previous
#include <cuda_runtime.h>
#include <math.h>

#define AT 48
#define SP 4
#define RCRf 5.2f
#define RCAf 3.5f
#define NSHFR 16
#define NSHFA 4
#define NSHFZ 8
#define RADSUB (SP * NSHFR)                 // 64
#define ANGSUB (NSHFA * NSHFZ)              // 32
#define NPAIRS_SP (SP * (SP + 1) / 2)       // 10
#define OUTW (RADSUB + NPAIRS_SP * ANGSUB)  // 384
#define PI_F 3.14159265358979f

__global__ __launch_bounds__(128) void aev_kernel(
    const float* __restrict__ coords,   // (M, A, 3)
    const float* __restrict__ gEtaR,    // (1,)
    const float* __restrict__ gShfR,    // (16,)
    const float* __restrict__ gEtaA,    // (1,)
    const float* __restrict__ gZeta,    // (1,)
    const float* __restrict__ gShfA,    // (4,)
    const float* __restrict__ gShfZ,    // (8,)
    const int*   __restrict__ species,  // (M, A)
    float* __restrict__ out)            // (M, A, 384)
{
    const int i = blockIdx.x;   // atom within molecule
    const int m = blockIdx.y;   // molecule
    const int tid = threadIdx.x;

    __shared__ float scx[AT], scy[AT], scz[AT];
    __shared__ int   ssp[AT];
    __shared__ float dds[AT];
    __shared__ float acc[OUTW];
    __shared__ float shfR[NSHFR], shfA[NSHFA], czv[NSHFZ], szv[NSHFZ];
    __shared__ float sEtaR, sEtaA, sZeta;

    // compacted angular neighbor list (d <= RCA, j != i)
    __shared__ int   nn;
    __shared__ float ndx[AT], ndy[AT], ndz[AT], nd[AT], nrd[AT], nfc[AT];
    __shared__ int   nsp[AT];

    // ---- stage molecule data + parameters ----
    if (tid < AT) {
        const float* c = coords + (size_t)(m * AT + tid) * 3;
        scx[tid] = c[0];
        scy[tid] = c[1];
        scz[tid] = c[2];
        ssp[tid] = species[m * AT + tid];
    }
    if (tid < NSHFR) shfR[tid] = gShfR[tid];
    if (tid < NSHFA) shfA[tid] = gShfA[tid];
    if (tid < NSHFZ) {
        float v = gShfZ[tid];
        czv[tid] = cosf(v);
        szv[tid] = sinf(v);
    }
    if (tid == 0) { sEtaR = gEtaR[0]; sEtaA = gEtaA[0]; sZeta = gZeta[0]; nn = 0; }
    for (int t = tid; t < OUTW; t += blockDim.x) acc[t] = 0.0f;
    __syncthreads();

    // ---- displacements from center atom i; compact angular neighbors ----
    if (tid < AT) {
        float dx = scx[tid] - scx[i];
        float dy = scy[tid] - scy[i];
        float dz = scz[tid] - scz[i];
        float d  = sqrtf(dx * dx + dy * dy + dz * dz);
        dds[tid] = d;
        if (tid != i && d <= RCAf) {
            int slot = atomicAdd(&nn, 1);
            ndx[slot] = dx; ndy[slot] = dy; ndz[slot] = dz;
            nd[slot]  = d;
            nrd[slot] = 1.0f / fmaxf(d, 1e-8f);
            nfc[slot] = 0.5f * __cosf(d * (PI_F / RCAf)) + 0.5f;
            nsp[slot] = ssp[tid];
        }
    }
    __syncthreads();

    const float etaR = sEtaR, etaA = sEtaA, zeta = sZeta;
    const bool zeta32 = (zeta == 32.0f);

    // ---- radial part: neighbors j of i ----
    if (tid < AT && tid != i) {
        const float d = dds[tid];
        if (d <= RCRf) {
            const float fc = 0.5f * __cosf(d * (PI_F / RCRf)) + 0.5f;
            float* dst = acc + ssp[tid] * NSHFR;
            #pragma unroll
            for (int s = 0; s < NSHFR; s++) {
                float t = d - shfR[s];
                float v = 0.25f * __expf(-etaR * t * t) * fc;
                atomicAdd(&dst[s], v);
            }
        }
    }

    // ---- angular part over compacted neighbors ----
    const int n = nn;
    const int np = (n * (n - 1)) >> 1;
    for (int p = tid; p < np; p += blockDim.x) {
        // decode p -> (j < k) over n compacted neighbors
        // cumulative pairs before row j: C(j) = j*(2n-1-j)/2
        float fn = (float)(2 * n - 1);
        int j = (int)((fn - sqrtf(fn * fn - 8.0f * (float)p)) * 0.5f);
        if (j < 0) j = 0;
        while (j > 0 && (j * (2 * n - 1 - j)) / 2 > p) j--;
        while (((j + 1) * (2 * n - 2 - j)) / 2 <= p) j++;
        int k = p - (j * (2 * n - 1 - j)) / 2 + j + 1;

        const float d1 = nd[j], d2 = nd[k];
        const float dot = ndx[j] * ndx[k] + ndy[j] * ndy[k] + ndz[j] * ndz[k];
        const float cosv = 0.95f * dot * nrd[j] * nrd[k];
        const float sinv = sqrtf(fmaxf(1.0f - cosv * cosv, 0.0f));
        const float fcj = nfc[j] * nfc[k];
        const float dm = 0.5f * (d1 + d2);

        float pre[NSHFA];
        #pragma unroll
        for (int a = 0; a < NSHFA; a++) {
            float t = dm - shfA[a];
            pre[a] = 2.0f * fcj * __expf(-etaA * t * t);
        }

        const int sa = nsp[j], sb = nsp[k];
        const int lo = min(sa, sb), hi = max(sa, sb);
        const int pidx = lo * SP - (lo * (lo - 1)) / 2 + (hi - lo);
        float* dst = acc + RADSUB + pidx * ANGSUB;

        #pragma unroll
        for (int z = 0; z < NSHFZ; z++) {
            // cos(theta - ShfZ[z]) expanded; sin(theta) >= 0 since theta in [0,pi]
            float cd = cosv * czv[z] + sinv * szv[z];
            float base = 0.5f * (1.0f + cd);
            float f1;
            if (zeta32) {
                // base^32 via 5 squarings (even power -> no clamp needed)
                float x = base;
                x *= x; x *= x; x *= x; x *= x; x *= x;
                f1 = x;
            } else {
                f1 = __powf(fmaxf(base, 0.0f), zeta);
            }
            #pragma unroll
            for (int a = 0; a < NSHFA; a++) {
                atomicAdd(&dst[a * NSHFZ + z], f1 * pre[a]);
            }
        }
    }

    __syncthreads();

    // ---- write out ----
    float* o = out + ((size_t)m * AT + i) * OUTW;
    for (int t = tid; t < OUTW; t += blockDim.x) o[t] = acc[t];
}

extern "C" void kernel_launch(void* const* d_in, const int* in_sizes, int n_in,
                              void* d_out, int out_size) {
    const float* coords = (const float*)d_in[0];
    const float* EtaR   = (const float*)d_in[1];
    const float* ShfR   = (const float*)d_in[2];
    const float* EtaA   = (const float*)d_in[3];
    const float* Zeta   = (const float*)d_in[4];
    const float* ShfA   = (const float*)d_in[5];
    const float* ShfZ   = (const float*)d_in[6];
    const int*   sp     = (const int*)d_in[7];
    float* out = (float*)d_out;

    const int M = in_sizes[0] / (AT * 3);
    dim3 grid(AT, M);
    aev_kernel<<<grid, 128>>>(coords, EtaR, ShfR, EtaA, Zeta, ShfA, ShfZ, sp, out);
}

// round 7
// speedup vs baseline: 3.8300x; 3.1161x over previous
#include <cuda_runtime.h>
#include <math.h>

#define AT 48
#define SP 4
#define RCRf 5.2f
#define RCAf 3.5f
#define NSHFR 16
#define NSHFA 4
#define NSHFZ 8
#define RADSUB (SP * NSHFR)                 // 64
#define ANGSUB (NSHFA * NSHFZ)              // 32
#define NPAIRS_SP (SP * (SP + 1) / 2)       // 10
#define OUTW (RADSUB + NPAIRS_SP * ANGSUB)  // 384
#define NPMAX (AT * (AT - 1) / 2)           // 1128 (worst case pair count)
#define NT 384
#define PI_F 3.14159265358979f

__global__ __launch_bounds__(NT) void aev_kernel(
    const float* __restrict__ coords,   // (M, A, 3)
    const float* __restrict__ gEtaR,    // (1,)
    const float* __restrict__ gShfR,    // (16,)
    const float* __restrict__ gEtaA,    // (1,)
    const float* __restrict__ gZeta,    // (1,)
    const float* __restrict__ gShfA,    // (4,)
    const float* __restrict__ gShfZ,    // (8,)
    const int*   __restrict__ species,  // (M, A)
    float* __restrict__ out)            // (M, A, 384)
{
    const int i = blockIdx.x;   // center atom within molecule
    const int m = blockIdx.y;   // molecule
    const int tid = threadIdx.x;

    __shared__ float scx[AT], scy[AT], scz[AT];
    __shared__ int   ssp[AT];
    __shared__ float dds[AT], rfc[AT];          // dist from i, radial cutoff fn
    __shared__ float shfR[NSHFR], shfA[NSHFA], czv[NSHFZ], szv[NSHFZ];
    __shared__ float sEtaR, sEtaA, sZeta;

    // compacted angular neighbor list (d <= RCA, j != i)
    __shared__ int   nn;
    __shared__ float adx[AT], ady[AT], adz[AT], ad[AT], ard[AT], afc[AT];
    __shared__ int   asp[AT];

    // per-pair precomputed data: {cos, sin, 2*fc1*fc2, dmean} + species-pair idx
    __shared__ float4        pdata[NPMAX];
    __shared__ unsigned char ppx[NPMAX];

    // ---- stage molecule data + parameters ----
    if (tid < AT) {
        const float* c = coords + (size_t)(m * AT + tid) * 3;
        scx[tid] = c[0];
        scy[tid] = c[1];
        scz[tid] = c[2];
        ssp[tid] = species[m * AT + tid];
    }
    if (tid < NSHFR) shfR[tid] = gShfR[tid];
    if (tid < NSHFA) shfA[tid] = gShfA[tid];
    if (tid < NSHFZ) {
        float v = gShfZ[tid];
        czv[tid] = cosf(v);
        szv[tid] = sinf(v);
    }
    if (tid == 0) { sEtaR = gEtaR[0]; sEtaA = gEtaA[0]; sZeta = gZeta[0]; nn = 0; }
    __syncthreads();

    // ---- distances from center i; compact angular neighbors ----
    if (tid < AT) {
        float dx = scx[tid] - scx[i];
        float dy = scy[tid] - scy[i];
        float dz = scz[tid] - scz[i];
        float d  = sqrtf(dx * dx + dy * dy + dz * dz);
        dds[tid] = d;
        rfc[tid] = 0.5f * __cosf(d * (PI_F / RCRf)) + 0.5f;
        if (tid != i && d <= RCAf) {
            int s = atomicAdd(&nn, 1);
            adx[s] = dx; ady[s] = dy; adz[s] = dz;
            ad[s]  = d;
            ard[s] = 1.0f / fmaxf(d, 1e-8f);
            afc[s] = 0.5f * __cosf(d * (PI_F / RCAf)) + 0.5f;
            asp[s] = ssp[tid];
        }
    }
    __syncthreads();

    const int n  = nn;
    const int np = (n * (n - 1)) >> 1;
    const float etaR = sEtaR, etaA = sEtaA, zeta = sZeta;

    // ---- per-pair precompute (no transcendentals beyond what's shared) ----
    for (int p = tid; p < np; p += NT) {
        // decode p -> (j < k); pairs before row j: j*(2n-1-j)/2
        float fn = (float)(2 * n - 1);
        int j = (int)((fn - sqrtf(fn * fn - 8.0f * (float)p)) * 0.5f);
        if (j < 0) j = 0;
        if (j > n - 2) j = n - 2;
        while (j > 0 && (j * (2 * n - 1 - j)) / 2 > p) j--;
        while (((j + 1) * (2 * n - 2 - j)) / 2 <= p) j++;
        int k = p - (j * (2 * n - 1 - j)) / 2 + j + 1;

        float dot  = adx[j] * adx[k] + ady[j] * ady[k] + adz[j] * adz[k];
        float cosv = 0.95f * dot * ard[j] * ard[k];
        float sinv = sqrtf(fmaxf(1.0f - cosv * cosv, 0.0f));
        float fcj2 = 2.0f * afc[j] * afc[k];
        float dm   = 0.5f * (ad[j] + ad[k]);
        pdata[p] = make_float4(cosv, sinv, fcj2, dm);

        int sa = asp[j], sb = asp[k];
        int lo = min(sa, sb), hi = max(sa, sb);
        ppx[p] = (unsigned char)(lo * SP - (lo * (lo - 1)) / 2 + (hi - lo));
    }
    __syncthreads();

    // ---- output-stationary gather: each thread owns one output element ----
    float* o = out + ((size_t)m * AT + i) * OUTW;
    float accv = 0.0f;

    if (tid < RADSUB) {
        // radial element (spb, shell)
        const int spb = tid >> 4;
        const int s   = tid & 15;
        const float sh = shfR[s];
        #pragma unroll 4
        for (int j = 0; j < AT; j++) {
            if (j == i) continue;
            float d = dds[j];
            if (d > RCRf || ssp[j] != spb) continue;
            float t = d - sh;
            accv += 0.25f * __expf(-etaR * t * t) * rfc[j];
        }
        o[tid] = accv;
    } else {
        // angular element (pidx, a, z); pidx is warp-uniform
        const int own  = tid - RADSUB;
        const int pidx = own >> 5;
        const int rr   = own & 31;
        const int a    = rr >> 3;
        const int z    = rr & 7;
        const float cz = czv[z], sz = szv[z], sh = shfA[a];
        const bool z32 = (zeta == 32.0f);

        for (int p = 0; p < np; p++) {
            if ((int)ppx[p] != pidx) continue;   // warp-uniform filter
            float4 pd = pdata[p];                // LDS.128 broadcast
            float cd   = pd.x * cz + pd.y * sz;  // cos(theta - ShfZ[z])
            float base = 0.5f + 0.5f * cd;
            float f1;
            if (z32) {
                float x = base;                   // even power: no clamp needed
                x *= x; x *= x; x *= x; x *= x; x *= x;
                f1 = x;
            } else {
                f1 = __powf(fmaxf(base, 0.0f), zeta);
            }
            float t = pd.w - sh;
            accv = fmaf(f1, pd.z * __expf(-etaA * t * t), accv);
        }
        o[RADSUB + own] = accv;
    }
}

extern "C" void kernel_launch(void* const* d_in, const int* in_sizes, int n_in,
                              void* d_out, int out_size) {
    const float* coords = (const float*)d_in[0];
    const float* EtaR   = (const float*)d_in[1];
    const float* ShfR   = (const float*)d_in[2];
    const float* EtaA   = (const float*)d_in[3];
    const float* Zeta   = (const float*)d_in[4];
    const float* ShfA   = (const float*)d_in[5];
    const float* ShfZ   = (const float*)d_in[6];
    const int*   sp     = (const int*)d_in[7];
    float* out = (float*)d_out;

    const int M = in_sizes[0] / (AT * 3);
    dim3 grid(AT, M);
    aev_kernel<<<grid, NT>>>(coords, EtaR, ShfR, EtaA, Zeta, ShfA, ShfZ, sp, out);
}

// round 8
// speedup vs baseline: 6.2018x; 1.6193x over previous
#include <cuda_runtime.h>
#include <math.h>

#define AT 48
#define SP 4
#define RCRf 5.2f
#define RCAf 3.5f
#define NSHFR 16
#define NSHFA 4
#define NSHFZ 8
#define RADSUB (SP * NSHFR)                 // 64
#define ANGSUB (NSHFA * NSHFZ)              // 32
#define NPAIRS_SP (SP * (SP + 1) / 2)       // 10
#define OUTW (RADSUB + NPAIRS_SP * ANGSUB)  // 384
#define NPMAX (AT * (AT - 1) / 2)           // 1128 (worst case pair count)
#define NT 384
#define NPPT 3                              // ceil(NPMAX / NT)
#define PI_F 3.14159265358979f

__global__ __launch_bounds__(NT) void aev_kernel(
    const float* __restrict__ coords,   // (M, A, 3)
    const float* __restrict__ gEtaR,    // (1,)
    const float* __restrict__ gShfR,    // (16,)
    const float* __restrict__ gEtaA,    // (1,)
    const float* __restrict__ gZeta,    // (1,)
    const float* __restrict__ gShfA,    // (4,)
    const float* __restrict__ gShfZ,    // (8,)
    const int*   __restrict__ species,  // (M, A)
    float* __restrict__ out)            // (M, A, 384)
{
    const int i = blockIdx.x;   // center atom within molecule
    const int m = blockIdx.y;   // molecule
    const int tid = threadIdx.x;

    __shared__ float scx[AT], scy[AT], scz[AT];
    __shared__ int   ssp[AT];
    __shared__ float shfR[NSHFR], shfA[NSHFA], czv[NSHFZ], szv[NSHFZ];
    __shared__ float sEtaR, sEtaA, sZeta;

    // radial neighbors bucketed by species: distance + 0.25*fc
    __shared__ int   rcnt[SP];
    __shared__ float rbd[SP * AT], rbf[SP * AT];

    // compacted angular neighbor list (d <= RCA, j != i)
    __shared__ int   nn;
    __shared__ float adx[AT], ady[AT], adz[AT], ad[AT], ard[AT], afc[AT];
    __shared__ int   asp[AT];

    // pairs bucket-sorted by species-pair index
    __shared__ int    acnt[NPAIRS_SP], abase[NPAIRS_SP], afill[NPAIRS_SP];
    __shared__ float4 pdata[NPMAX];     // {cos, sin, 2*fc1*fc2, dmean}

    // ---- stage molecule data + parameters ----
    if (tid < AT) {
        const float* c = coords + (size_t)(m * AT + tid) * 3;
        scx[tid] = c[0];
        scy[tid] = c[1];
        scz[tid] = c[2];
        ssp[tid] = species[m * AT + tid];
    }
    if (tid < NSHFR) shfR[tid] = gShfR[tid];
    if (tid < NSHFA) shfA[tid] = gShfA[tid];
    if (tid < NSHFZ) {
        float v = gShfZ[tid];
        czv[tid] = cosf(v);
        szv[tid] = sinf(v);
    }
    if (tid < NPAIRS_SP) acnt[tid] = 0;
    if (tid < SP) rcnt[tid] = 0;
    if (tid == 0) { sEtaR = gEtaR[0]; sEtaA = gEtaA[0]; sZeta = gZeta[0]; nn = 0; }
    __syncthreads();

    // ---- distances from center i; compact radial + angular neighbors ----
    if (tid < AT && tid != i) {
        float dx = scx[tid] - scx[i];
        float dy = scy[tid] - scy[i];
        float dz = scz[tid] - scz[i];
        float d  = sqrtf(dx * dx + dy * dy + dz * dz);
        if (d <= RCRf) {
            float fc = 0.5f * __cosf(d * (PI_F / RCRf)) + 0.5f;
            int sp_ = ssp[tid];
            int s = atomicAdd(&rcnt[sp_], 1);
            rbd[sp_ * AT + s] = d;
            rbf[sp_ * AT + s] = 0.25f * fc;
        }
        if (d <= RCAf) {
            int s = atomicAdd(&nn, 1);
            adx[s] = dx; ady[s] = dy; adz[s] = dz;
            ad[s]  = d;
            ard[s] = 1.0f / fmaxf(d, 1e-8f);
            afc[s] = 0.5f * __cosf(d * (PI_F / RCAf)) + 0.5f;
            asp[s] = ssp[tid];
        }
    }
    __syncthreads();

    const int n  = nn;
    const int np = (n * (n - 1)) >> 1;
    const float etaR = sEtaR, etaA = sEtaA, zeta = sZeta;

    // ---- per-pair precompute into registers + bucket counts ----
    float4 lf4[NPPT];
    int    lpx[NPPT];
    #pragma unroll
    for (int t = 0; t < NPPT; t++) {
        lpx[t] = -1;
        int p = tid + t * NT;
        if (p < np) {
            // decode p -> (j < k); pairs before row j: j*(2n-1-j)/2
            float fn = (float)(2 * n - 1);
            int j = (int)((fn - sqrtf(fn * fn - 8.0f * (float)p)) * 0.5f);
            if (j < 0) j = 0;
            if (j > n - 2) j = n - 2;
            while (j > 0 && (j * (2 * n - 1 - j)) / 2 > p) j--;
            while (((j + 1) * (2 * n - 2 - j)) / 2 <= p) j++;
            int k = p - (j * (2 * n - 1 - j)) / 2 + j + 1;

            float dot  = adx[j] * adx[k] + ady[j] * ady[k] + adz[j] * adz[k];
            float cosv = 0.95f * dot * ard[j] * ard[k];
            float sinv = sqrtf(fmaxf(1.0f - cosv * cosv, 0.0f));
            float fcj2 = 2.0f * afc[j] * afc[k];
            float dm   = 0.5f * (ad[j] + ad[k]);
            lf4[t] = make_float4(cosv, sinv, fcj2, dm);

            int sa = asp[j], sb = asp[k];
            int lo = min(sa, sb), hi = max(sa, sb);
            int px = lo * SP - (lo * (lo - 1)) / 2 + (hi - lo);
            lpx[t] = px;
            atomicAdd(&acnt[px], 1);
        }
    }
    __syncthreads();

    if (tid == 0) {
        int run = 0;
        #pragma unroll
        for (int q = 0; q < NPAIRS_SP; q++) {
            abase[q] = run;
            afill[q] = run;
            run += acnt[q];
        }
    }
    __syncthreads();

    #pragma unroll
    for (int t = 0; t < NPPT; t++) {
        if (lpx[t] >= 0) {
            int dst = atomicAdd(&afill[lpx[t]], 1);
            pdata[dst] = lf4[t];
        }
    }
    __syncthreads();

    // ---- output-stationary gather: each thread owns one output element ----
    float* o = out + ((size_t)m * AT + i) * OUTW;
    float accv = 0.0f;

    if (tid < RADSUB) {
        // radial element (species, shell): branch-free bucket scan
        const int spb = tid >> 4;
        const int s   = tid & 15;
        const float sh = shfR[s];
        const int cnt = rcnt[spb];
        const float* bd = rbd + spb * AT;
        const float* bf = rbf + spb * AT;
        for (int j = 0; j < cnt; j++) {
            float t = bd[j] - sh;
            accv = fmaf(bf[j], __expf(-etaR * t * t), accv);
        }
        o[tid] = accv;
    } else {
        // angular element (pidx, a, z); pidx is warp-uniform -> own bucket only
        const int own  = tid - RADSUB;
        const int pidx = own >> 5;
        const int rr   = own & 31;
        const int a    = rr >> 3;
        const int z    = rr & 7;
        const float cz = czv[z], sz = szv[z], sh = shfA[a];
        const bool z32 = (zeta == 32.0f);

        const int pb = abase[pidx];
        const int pe = pb + acnt[pidx];
        for (int p = pb; p < pe; p++) {
            float4 pd = pdata[p];                // broadcast LDS.128
            float cd   = pd.x * cz + pd.y * sz;  // cos(theta - ShfZ[z])
            float base = 0.5f + 0.5f * cd;
            float f1;
            if (z32) {
                float x = base;                   // even power: no clamp needed
                x *= x; x *= x; x *= x; x *= x; x *= x;
                f1 = x;
            } else {
                f1 = __powf(fmaxf(base, 0.0f), zeta);
            }
            float t = pd.w - sh;
            accv = fmaf(f1, pd.z * __expf(-etaA * t * t), accv);
        }
        o[RADSUB + own] = accv;
    }
}

extern "C" void kernel_launch(void* const* d_in, const int* in_sizes, int n_in,
                              void* d_out, int out_size) {
    const float* coords = (const float*)d_in[0];
    const float* EtaR   = (const float*)d_in[1];
    const float* ShfR   = (const float*)d_in[2];
    const float* EtaA   = (const float*)d_in[3];
    const float* Zeta   = (const float*)d_in[4];
    const float* ShfA   = (const float*)d_in[5];
    const float* ShfZ   = (const float*)d_in[6];
    const int*   sp     = (const int*)d_in[7];
    float* out = (float*)d_out;

    const int M = in_sizes[0] / (AT * 3);
    dim3 grid(AT, M);
    aev_kernel<<<grid, NT>>>(coords, EtaR, ShfR, EtaA, Zeta, ShfA, ShfZ, sp, out);
}

// round 12
// speedup vs baseline: 6.5000x; 1.0481x over previous
#include <cuda_runtime.h>
#include <math.h>

#define AT 48
#define SP 4
#define RCRf 5.2f
#define RCAf 3.5f
#define NSHFR 16
#define NSHFA 4
#define NSHFZ 8
#define RADSUB (SP * NSHFR)                 // 64
#define ANGSUB (NSHFA * NSHFZ)              // 32
#define NPAIRS_SP (SP * (SP + 1) / 2)       // 10
#define OUTW (RADSUB + NPAIRS_SP * ANGSUB)  // 384
#define NPMAX (AT * (AT - 1) / 2)           // 1128 (worst case pair count)
#define NT 256
#define PI_F 3.14159265358979f

struct SmemLayout {
    float  shfR[NSHFR], shfA[NSHFA], czv[NSHFZ], szv[NSHFZ];
    float  sEtaR, sEtaA, sZeta;
    // radial neighbors bucketed by species: {d, 0.25*fc}
    int    rcnt[SP];
    float2 rbdf[SP * AT];
    // compacted angular neighbor list (d <= RCA, j != i)
    int    nn;
    float  adx[AT], ady[AT], adz[AT], ad[AT], ard[AT], afc[AT];
    int    asp[AT];
    // pair data (unsorted) + species-pair id + sorted index order
    float4         pdata[NPMAX];   // {cos, sin, 2*fc1*fc2, dmean}
    unsigned char  ppx[NPMAX];
    unsigned short ord[NPMAX];
    int    acnt[NPAIRS_SP], abase[NPAIRS_SP], afill[NPAIRS_SP];
};

__device__ __forceinline__ float gather_one(
    const SmemLayout* sm, int o, float etaR, float etaA, float zeta, bool z32)
{
    float accv = 0.0f;
    if (o < RADSUB) {
        const int spb = o >> 4;
        const int s   = o & 15;
        const float sh = sm->shfR[s];
        const int cnt = sm->rcnt[spb];
        const float2* b = sm->rbdf + spb * AT;
        for (int j = 0; j < cnt; j++) {
            float2 df = b[j];
            float t = df.x - sh;
            accv = fmaf(df.y, __expf(-etaR * t * t), accv);
        }
    } else {
        const int own  = o - RADSUB;
        const int pidx = own >> 5;
        const int rr   = own & 31;
        const int a    = rr >> 3;
        const int z    = rr & 7;
        const float cz = sm->czv[z], sz = sm->szv[z], sh = sm->shfA[a];
        const int pb = sm->abase[pidx];
        const int pe = pb + sm->acnt[pidx];
        for (int q = pb; q < pe; q++) {
            float4 pd = sm->pdata[sm->ord[q]];   // broadcast LDS.128
            float cd   = pd.x * cz + pd.y * sz;  // cos(theta - ShfZ[z])
            float base = 0.5f + 0.5f * cd;
            float f1;
            if (z32) {
                float x = base;                  // base^32: even power, no clamp
                x *= x; x *= x; x *= x; x *= x; x *= x;
                f1 = x;
            } else {
                f1 = __powf(fmaxf(base, 0.0f), zeta);
            }
            float t = pd.w - sh;
            accv = fmaf(f1, pd.z * __expf(-etaA * t * t), accv);
        }
    }
    return accv;
}

__global__ __launch_bounds__(NT) void aev_kernel(
    const float* __restrict__ coords,   // (M, A, 3)
    const float* __restrict__ gEtaR,
    const float* __restrict__ gShfR,
    const float* __restrict__ gEtaA,
    const float* __restrict__ gZeta,
    const float* __restrict__ gShfA,
    const float* __restrict__ gShfZ,
    const int*   __restrict__ species,  // (M, A)
    float* __restrict__ out)            // (M, A, 384)
{
    const int i = blockIdx.x;
    const int m = blockIdx.y;
    const int tid = threadIdx.x;

    __shared__ SmemLayout sm;

    // ---- phase 0: params + counter init (counters MUST be visible before
    //      any compaction atomics -> barrier below is load-bearing) ----
    if (tid < NSHFR) sm.shfR[tid] = gShfR[tid];
    if (tid < NSHFA) sm.shfA[tid] = gShfA[tid];
    if (tid < NSHFZ) __sincosf(gShfZ[tid], &sm.szv[tid], &sm.czv[tid]);
    if (tid < NPAIRS_SP) sm.acnt[tid] = 0;
    if (tid < SP) sm.rcnt[tid] = 0;
    if (tid == 0) {
        sm.sEtaR = gEtaR[0]; sm.sEtaA = gEtaA[0]; sm.sZeta = gZeta[0]; sm.nn = 0;
    }
    __syncthreads();

    // ---- phase 1: distances from center i; compact radial + angular ----
    if (tid < AT && tid != i) {
        const float* cj = coords + (size_t)(m * AT + tid) * 3;
        const float* ci = coords + (size_t)(m * AT + i) * 3;   // broadcast, cached
        float dx = cj[0] - ci[0];
        float dy = cj[1] - ci[1];
        float dz = cj[2] - ci[2];
        float d  = sqrtf(dx * dx + dy * dy + dz * dz);
        int sp_  = species[m * AT + tid];
        if (d <= RCRf) {
            float fc = 0.5f * __cosf(d * (PI_F / RCRf)) + 0.5f;
            int s = atomicAdd(&sm.rcnt[sp_], 1);
            sm.rbdf[sp_ * AT + s] = make_float2(d, 0.25f * fc);
        }
        if (d <= RCAf) {
            int s = atomicAdd(&sm.nn, 1);
            sm.adx[s] = dx; sm.ady[s] = dy; sm.adz[s] = dz;
            sm.ad[s]  = d;
            sm.ard[s] = 1.0f / fmaxf(d, 1e-8f);
            sm.afc[s] = 0.5f * __cosf(d * (PI_F / RCAf)) + 0.5f;
            sm.asp[s] = sp_;
        }
    }
    __syncthreads();

    const int n  = sm.nn;
    const int np = (n * (n - 1)) >> 1;
    const float etaR = sm.sEtaR, etaA = sm.sEtaA, zeta = sm.sZeta;
    const bool z32 = (zeta == 32.0f);

    // ---- phase 2: per-pair precompute (unsorted) + bucket counts ----
    for (int p = tid; p < np; p += NT) {
        // decode p -> (j < k); pairs before row j: j*(2n-1-j)/2
        float fn = (float)(2 * n - 1);
        int j = (int)((fn - sqrtf(fn * fn - 8.0f * (float)p)) * 0.5f);
        if (j < 0) j = 0;
        if (j > n - 2) j = n - 2;
        while (j > 0 && (j * (2 * n - 1 - j)) / 2 > p) j--;
        while (((j + 1) * (2 * n - 2 - j)) / 2 <= p) j++;
        int k = p - (j * (2 * n - 1 - j)) / 2 + j + 1;

        float dot  = sm.adx[j] * sm.adx[k] + sm.ady[j] * sm.ady[k] + sm.adz[j] * sm.adz[k];
        float cosv = 0.95f * dot * sm.ard[j] * sm.ard[k];
        float sinv = sqrtf(fmaxf(1.0f - cosv * cosv, 0.0f));
        float fcj2 = 2.0f * sm.afc[j] * sm.afc[k];
        float dm   = 0.5f * (sm.ad[j] + sm.ad[k]);
        sm.pdata[p] = make_float4(cosv, sinv, fcj2, dm);

        int sa = sm.asp[j], sb = sm.asp[k];
        int lo = min(sa, sb), hi = max(sa, sb);
        int px = lo * SP - (lo * (lo - 1)) / 2 + (hi - lo);
        sm.ppx[p] = (unsigned char)px;
        atomicAdd(&sm.acnt[px], 1);
    }
    __syncthreads();

    if (tid == 0) {
        int run = 0;
        #pragma unroll
        for (int q = 0; q < NPAIRS_SP; q++) {
            sm.abase[q] = run;
            sm.afill[q] = run;
            run += sm.acnt[q];
        }
    }
    __syncthreads();

    // ---- phase 3: scatter sorted indices ----
    for (int p = tid; p < np; p += NT) {
        int dst = atomicAdd(&sm.afill[sm.ppx[p]], 1);
        sm.ord[dst] = (unsigned short)p;
    }
    __syncthreads();

    // ---- phase 4: output-stationary gather ----
    float* o = out + ((size_t)m * AT + i) * OUTW;
    o[tid] = gather_one(&sm, tid, etaR, etaA, zeta, z32);
    if (tid < OUTW - NT) {
        o[NT + tid] = gather_one(&sm, NT + tid, etaR, etaA, zeta, z32);
    }
}

extern "C" void kernel_launch(void* const* d_in, const int* in_sizes, int n_in,
                              void* d_out, int out_size) {
    const float* coords = (const float*)d_in[0];
    const float* EtaR   = (const float*)d_in[1];
    const float* ShfR   = (const float*)d_in[2];
    const float* EtaA   = (const float*)d_in[3];
    const float* Zeta   = (const float*)d_in[4];
    const float* ShfA   = (const float*)d_in[5];
    const float* ShfZ   = (const float*)d_in[6];
    const int*   sp     = (const int*)d_in[7];
    float* out = (float*)d_out;

    const int M = in_sizes[0] / (AT * 3);
    dim3 grid(AT, M);
    aev_kernel<<<grid, NT>>>(coords, EtaR, ShfR, EtaA, Zeta, ShfA, ShfZ, sp, out);
}